// round 5
// baseline (speedup 1.0000x reference)
#include <cuda_runtime.h>
#include <math.h>

// Problem constants
#define B_    2048
#define S_    134
#define E_    256
#define H_    1024
#define T_    5
#define K_    6
#define M_TOT (B_ * T_)      // 10240 rows
#define NCAT  (E_ + H_)      // 1280
#define NTOT  (2 * H_)       // 2048 (ld | sd halves of H_pre)

// d_out layout: kp_loss(1), logits(B,T,K,2), scores(B,T,K), selected(B,T,2), loss_per_kp(T)
#define OFF_LOGITS 1
#define OFF_SCORES (OFF_LOGITS + M_TOT * 2 * K_)   // 1 + 122880 = 122881
#define OFF_SEL    (OFF_SCORES + M_TOT * K_)       // 184321
#define OFF_LPK    (OFF_SEL + M_TOT * 2)           // 204801

// Scratch (static device globals: no allocations allowed)
__device__ float g_Hpre[(size_t)M_TOT * NTOT];     // 84 MB
__device__ float g_minloss[M_TOT];
__device__ float g_ce[M_TOT];
__device__ float g_w2t_ld[12 * NCAT];              // transposed [o][k]
__device__ float g_w2t_sd[6 * NCAT];

// ---------------------------------------------------------------------------
// Kernel 0: transpose w2 so GEMM2 reads are coalesced / L1-resident
// ---------------------------------------------------------------------------
__global__ void k_w2t(const float* __restrict__ ldw2, const float* __restrict__ sdw2) {
    int i = blockIdx.x * blockDim.x + threadIdx.x;
    if (i < 12 * NCAT) {
        int k = i / 12, o = i % 12;
        g_w2t_ld[o * NCAT + k] = ldw2[i];
    }
    if (i < 6 * NCAT) {
        int k = i / 6, o = i % 6;
        g_w2t_sd[o * NCAT + k] = sdw2[i];
    }
}

// ---------------------------------------------------------------------------
// Kernel A: H_pre[10240,2048] = X_slice @ [ld_w1 | sd_w1] + [ld_b1 | sd_b1]
// Classic fp32 SGEMM: BM=128 BN=128 BK=16, 8x8 microtile, 256 threads.
// ---------------------------------------------------------------------------
#define BM 128
#define BN 128
#define BK 16
#define TM 8
#define TN 8

__global__ __launch_bounds__(256, 2)
void k_gemm1(const float* __restrict__ hidden,
             const float* __restrict__ ldw1, const float* __restrict__ ldb1,
             const float* __restrict__ sdw1, const float* __restrict__ sdb1,
             const int* __restrict__ ctx)
{
    __shared__ float As[BK][BM + 4];
    __shared__ float Bs[BK][BN];

    const int tid = threadIdx.x;
    const int bx = blockIdx.x;   // 0..15 : column tile of H_pre
    const int by = blockIdx.y;   // 0..79 : row tile
    const int kp_start = ctx[0] - 1;

    const float* W    = (bx < 8) ? ldw1 : sdw1;
    const float* bias = (bx < 8) ? ldb1 : sdb1;
    const int nloc0   = (bx < 8) ? bx * BN : (bx - 8) * BN;

    const int m0 = by * BM;

    // A-tile loads: 2 float4 per thread, rows a_row and a_row+64
    const int a_row = tid >> 2;            // 0..63
    const int a_c4  = (tid & 3) * 4;       // 0,4,8,12
    size_t rowA0, rowA1;
    {
        int m = m0 + a_row;
        int b = m / T_, t = m - b * T_;
        rowA0 = (size_t)(b * S_ + kp_start + t) * E_;
        m += 64; b = m / T_; t = m - b * T_;
        rowA1 = (size_t)(b * S_ + kp_start + t) * E_;
    }
    // B-tile loads: 2 float4 per thread (k rows b_k and b_k+8)
    const int b_k  = tid >> 5;             // 0..7
    const int b_n4 = (tid & 31) * 4;       // 0..124

    const int tx = tid & 15;
    const int ty = tid >> 4;

    float acc[TM][TN];
#pragma unroll
    for (int i = 0; i < TM; i++)
#pragma unroll
        for (int j = 0; j < TN; j++) acc[i][j] = 0.f;

    for (int k0 = 0; k0 < E_; k0 += BK) {
        float4 a0 = *(const float4*)(hidden + rowA0 + k0 + a_c4);
        float4 a1 = *(const float4*)(hidden + rowA1 + k0 + a_c4);
        As[a_c4 + 0][a_row]      = a0.x;
        As[a_c4 + 1][a_row]      = a0.y;
        As[a_c4 + 2][a_row]      = a0.z;
        As[a_c4 + 3][a_row]      = a0.w;
        As[a_c4 + 0][a_row + 64] = a1.x;
        As[a_c4 + 1][a_row + 64] = a1.y;
        As[a_c4 + 2][a_row + 64] = a1.z;
        As[a_c4 + 3][a_row + 64] = a1.w;

        float4 w0 = *(const float4*)(W + (size_t)(k0 + b_k)     * H_ + nloc0 + b_n4);
        float4 w1 = *(const float4*)(W + (size_t)(k0 + b_k + 8) * H_ + nloc0 + b_n4);
        *(float4*)&Bs[b_k][b_n4]     = w0;
        *(float4*)&Bs[b_k + 8][b_n4] = w1;
        __syncthreads();

#pragma unroll
        for (int kk = 0; kk < BK; kk++) {
            float4 ra0 = *(const float4*)&As[kk][ty * TM];
            float4 ra1 = *(const float4*)&As[kk][ty * TM + 4];
            float4 rb0 = *(const float4*)&Bs[kk][tx * TN];
            float4 rb1 = *(const float4*)&Bs[kk][tx * TN + 4];
            float ra[8] = {ra0.x, ra0.y, ra0.z, ra0.w, ra1.x, ra1.y, ra1.z, ra1.w};
            float rb[8] = {rb0.x, rb0.y, rb0.z, rb0.w, rb1.x, rb1.y, rb1.z, rb1.w};
#pragma unroll
            for (int i = 0; i < TM; i++)
#pragma unroll
                for (int j = 0; j < TN; j++)
                    acc[i][j] = fmaf(ra[i], rb[j], acc[i][j]);
        }
        __syncthreads();
    }

    // epilogue: add bias, store
#pragma unroll
    for (int i = 0; i < TM; i++) {
        int m = m0 + ty * TM + i;
        float* dst = g_Hpre + (size_t)m * NTOT + bx * BN + tx * TN;
        float4 o0, o1;
        o0.x = acc[i][0] + bias[nloc0 + tx * TN + 0];
        o0.y = acc[i][1] + bias[nloc0 + tx * TN + 1];
        o0.z = acc[i][2] + bias[nloc0 + tx * TN + 2];
        o0.w = acc[i][3] + bias[nloc0 + tx * TN + 3];
        o1.x = acc[i][4] + bias[nloc0 + tx * TN + 4];
        o1.y = acc[i][5] + bias[nloc0 + tx * TN + 5];
        o1.z = acc[i][6] + bias[nloc0 + tx * TN + 6];
        o1.w = acc[i][7] + bias[nloc0 + tx * TN + 7];
        *(float4*)dst       = o0;
        *(float4*)(dst + 4) = o1;
    }
}

// ---------------------------------------------------------------------------
// Kernel B: per-row LayerNorm + relu + GEMM2 (out = cat([x,h]) @ w2 + b2)
// One block (256 thr) per row. Writes logits and scores directly into d_out.
// ---------------------------------------------------------------------------
__global__ __launch_bounds__(256)
void k_ln_gemm2(const float* __restrict__ hidden,
                const float* __restrict__ ldg, const float* __restrict__ ldbeta,
                const float* __restrict__ ldb2,
                const float* __restrict__ sdg, const float* __restrict__ sdbeta,
                const float* __restrict__ sdb2,
                const int* __restrict__ ctx,
                float* __restrict__ out)
{
    __shared__ float xs[E_];
    __shared__ float actld[H_];
    __shared__ float actsd[H_];
    __shared__ float red[8][4];
    __shared__ float stats[4];

    const int m   = blockIdx.x;
    const int tid = threadIdx.x;
    const int kp_start = ctx[0] - 1;
    const int b = m / T_, t = m - b * T_;
    const float* xrow = hidden + (size_t)(b * S_ + kp_start + t) * E_;
    xs[tid] = xrow[tid];                       // 256 threads == E_

    const float* hrow = g_Hpre + (size_t)m * NTOT;
    float hl[4], hs[4];
    float s1 = 0.f, s2 = 0.f, s3 = 0.f, s4 = 0.f;
#pragma unroll
    for (int i = 0; i < 4; i++) {
        int j = tid + 256 * i;
        hl[i] = hrow[j];
        hs[i] = hrow[H_ + j];
        s1 += hl[i]; s2 += hl[i] * hl[i];
        s3 += hs[i]; s4 += hs[i] * hs[i];
    }
#pragma unroll
    for (int o = 16; o; o >>= 1) {
        s1 += __shfl_down_sync(0xffffffffu, s1, o);
        s2 += __shfl_down_sync(0xffffffffu, s2, o);
        s3 += __shfl_down_sync(0xffffffffu, s3, o);
        s4 += __shfl_down_sync(0xffffffffu, s4, o);
    }
    const int w = tid >> 5, l = tid & 31;
    if (l == 0) { red[w][0] = s1; red[w][1] = s2; red[w][2] = s3; red[w][3] = s4; }
    __syncthreads();
    if (tid == 0) {
        float a = 0.f, bb = 0.f, c = 0.f, d = 0.f;
        for (int i = 0; i < 8; i++) { a += red[i][0]; bb += red[i][1]; c += red[i][2]; d += red[i][3]; }
        float mul = a / H_, mus = c / H_;
        float varl = bb / H_ - mul * mul;
        float vars = d / H_ - mus * mus;
        stats[0] = mul; stats[1] = rsqrtf(varl + 1e-5f);
        stats[2] = mus; stats[3] = rsqrtf(vars + 1e-5f);
    }
    __syncthreads();
    const float mul = stats[0], rl = stats[1], mus = stats[2], rs = stats[3];
#pragma unroll
    for (int i = 0; i < 4; i++) {
        int j = tid + 256 * i;
        float a = ldg[j] * (hl[i] - mul) * rl + ldbeta[j];
        actld[j] = fmaxf(a, 0.f);
        float c = sdg[j] * (hs[i] - mus) * rs + sdbeta[j];
        actsd[j] = fmaxf(c, 0.f);
    }
    __syncthreads();

    // GEMM2: warps 0-5 -> 12 logits outputs, warps 6-7 -> 6 score outputs.
    if (w < 6) {
#pragma unroll
        for (int oo = 0; oo < 2; oo++) {
            const int o = 2 * w + oo;
            const float* wcol = g_w2t_ld + (size_t)o * NCAT;
            float acc = 0.f;
#pragma unroll
            for (int i = 0; i < 40; i++) {
                int k = l + 32 * i;
                float v = (k < E_) ? xs[k] : actld[k - E_];
                acc = fmaf(v, __ldg(wcol + k), acc);
            }
#pragma unroll
            for (int off = 16; off; off >>= 1) acc += __shfl_down_sync(0xffffffffu, acc, off);
            if (l == 0) out[OFF_LOGITS + (size_t)m * 12 + o] = acc + __ldg(ldb2 + o);
        }
    } else {
#pragma unroll
        for (int oo = 0; oo < 3; oo++) {
            const int o = 3 * (w - 6) + oo;
            const float* wcol = g_w2t_sd + (size_t)o * NCAT;
            float acc = 0.f;
#pragma unroll
            for (int i = 0; i < 40; i++) {
                int k = l + 32 * i;
                float v = (k < E_) ? xs[k] : actsd[k - E_];
                acc = fmaf(v, __ldg(wcol + k), acc);
            }
#pragma unroll
            for (int off = 16; off; off >>= 1) acc += __shfl_down_sync(0xffffffffu, acc, off);
            if (l == 0) out[OFF_SCORES + (size_t)m * 6 + o] = acc + __ldg(sdb2 + o);
        }
    }
}

// ---------------------------------------------------------------------------
// Kernel C: per-(b,t) loss: min/argmin over K modes, double-softmax CE, selected
// ---------------------------------------------------------------------------
__global__ void k_loss(const float* __restrict__ fkp, float* __restrict__ out)
{
    int m = blockIdx.x * blockDim.x + threadIdx.x;
    if (m >= M_TOT) return;

    const float* lg = out + OFF_LOGITS + (size_t)m * 12;
    const float* sc = out + OFF_SCORES + (size_t)m * 6;
    float fx = fkp[m * 2 + 0], fy = fkp[m * 2 + 1];

    float l[12], s[6];
#pragma unroll
    for (int i = 0; i < 12; i++) l[i] = lg[i];
#pragma unroll
    for (int i = 0; i < 6; i++)  s[i] = sc[i];

    float best = 3.4e38f; int bi = 0;
#pragma unroll
    for (int k = 0; k < K_; k++) {
        float dx = l[2 * k] - fx, dy = l[2 * k + 1] - fy;
        float v = dx * dx + dy * dy;
        if (v < best) { best = v; bi = k; }
    }

    // softmax(scores)
    float mx = s[0];
#pragma unroll
    for (int k = 1; k < K_; k++) mx = fmaxf(mx, s[k]);
    float Z = 0.f, e[6];
#pragma unroll
    for (int k = 0; k < K_; k++) { e[k] = expf(s[k] - mx); Z += e[k]; }
    float sm[6];
#pragma unroll
    for (int k = 0; k < K_; k++) sm[k] = e[k] / Z;
    // log_softmax(softmax(scores)) at index bi
    float mx2 = sm[0];
#pragma unroll
    for (int k = 1; k < K_; k++) mx2 = fmaxf(mx2, sm[k]);
    float Z2 = 0.f;
#pragma unroll
    for (int k = 0; k < K_; k++) Z2 += expf(sm[k] - mx2);
    float ce = -(sm[bi] - mx2 - logf(Z2));

    out[OFF_SEL + (size_t)m * 2 + 0] = l[2 * bi];
    out[OFF_SEL + (size_t)m * 2 + 1] = l[2 * bi + 1];
    g_minloss[m] = best;
    g_ce[m]      = ce;
}

// ---------------------------------------------------------------------------
// Kernel D: deterministic reduction over B per t, loss_per_kp and kp_loss
// ---------------------------------------------------------------------------
__global__ void k_loss_reduce(float* __restrict__ out)
{
    __shared__ float red[16];
    __shared__ float lpk[T_];
    const int tid = threadIdx.x;
    const float wt[T_] = {1e-4f, 1e-3f, 1e-2f, 1e-1f, 1.f};

    for (int t = 0; t < T_; t++) {
        float sm = 0.f, sc = 0.f;
        for (int b = tid; b < B_; b += 256) {
            sm += g_minloss[b * T_ + t];
            sc += g_ce[b * T_ + t];
        }
#pragma unroll
        for (int o = 16; o; o >>= 1) {
            sm += __shfl_down_sync(0xffffffffu, sm, o);
            sc += __shfl_down_sync(0xffffffffu, sc, o);
        }
        int w = tid >> 5, l = tid & 31;
        if (l == 0) { red[w] = sm; red[w + 8] = sc; }
        __syncthreads();
        if (tid == 0) {
            float a = 0.f, c = 0.f;
            for (int i = 0; i < 8; i++) { a += red[i]; c += red[i + 8]; }
            float v = (a / (float)B_) * wt[t] + c / (float)B_;
            lpk[t] = v;
            out[OFF_LPK + t] = v;
        }
        __syncthreads();
    }
    if (tid == 0) {
        float s = 0.f;
        for (int t = 0; t < T_; t++) s += lpk[t];
        out[0] = s / (float)T_;
    }
}

// ---------------------------------------------------------------------------
extern "C" void kernel_launch(void* const* d_in, const int* in_sizes, int n_in,
                              void* d_out, int out_size)
{
    const float* hidden  = (const float*)d_in[0];
    const float* fkp     = (const float*)d_in[1];
    const float* ld_w1   = (const float*)d_in[2];
    const float* ld_b1   = (const float*)d_in[3];
    const float* ld_g    = (const float*)d_in[4];
    const float* ld_be   = (const float*)d_in[5];
    const float* ld_w2   = (const float*)d_in[6];
    const float* ld_b2   = (const float*)d_in[7];
    const float* sd_w1   = (const float*)d_in[8];
    const float* sd_b1   = (const float*)d_in[9];
    const float* sd_g    = (const float*)d_in[10];
    const float* sd_be   = (const float*)d_in[11];
    const float* sd_w2   = (const float*)d_in[12];
    const float* sd_b2   = (const float*)d_in[13];
    const int*   ctx     = (const int*)d_in[14];
    float* out = (float*)d_out;

    k_w2t<<<(12 * NCAT + 255) / 256, 256>>>(ld_w2, sd_w2);
    dim3 gridA(NTOT / BN, M_TOT / BM);   // (16, 80)
    k_gemm1<<<gridA, 256>>>(hidden, ld_w1, ld_b1, sd_w1, sd_b1, ctx);
    k_ln_gemm2<<<M_TOT, 256>>>(hidden, ld_g, ld_be, ld_b2, sd_g, sd_be, sd_b2, ctx, out);
    k_loss<<<(M_TOT + 255) / 256, 256>>>(fkp, out);
    k_loss_reduce<<<1, 256>>>(out);
}

// round 6
// speedup vs baseline: 1.0031x; 1.0031x over previous
#include <cuda_runtime.h>
#include <math.h>

// Problem constants
#define B_    2048
#define S_    134
#define E_    256
#define H_    1024
#define T_    5
#define K_    6
#define M_TOT (B_ * T_)      // 10240 rows
#define NCAT  (E_ + H_)      // 1280
#define NTOT  (2 * H_)       // 2048 (ld | sd halves of H_pre)

// d_out layout: kp_loss(1), logits(B,T,K,2), scores(B,T,K), selected(B,T,2), loss_per_kp(T)
#define OFF_LOGITS 1
#define OFF_SCORES (OFF_LOGITS + M_TOT * 2 * K_)   // 1 + 122880 = 122881
#define OFF_SEL    (OFF_SCORES + M_TOT * K_)       // 184321
#define OFF_LPK    (OFF_SEL + M_TOT * 2)           // 204801

// Scratch (static device globals: no allocations allowed)
__device__ float g_Hpre[(size_t)M_TOT * NTOT];     // 84 MB
__device__ float g_minloss[M_TOT];
__device__ float g_ce[M_TOT];
__device__ float g_w2t_ld[12 * NCAT];              // transposed [o][k]
__device__ float g_w2t_sd[6 * NCAT];

// ---------------------------------------------------------------------------
// Kernel 0: transpose w2 so GEMM2 reads are coalesced / L1-resident
// ---------------------------------------------------------------------------
__global__ void k_w2t(const float* __restrict__ ldw2, const float* __restrict__ sdw2) {
    int i = blockIdx.x * blockDim.x + threadIdx.x;
    if (i < 12 * NCAT) {
        int k = i / 12, o = i % 12;
        g_w2t_ld[o * NCAT + k] = ldw2[i];
    }
    if (i < 6 * NCAT) {
        int k = i / 6, o = i % 6;
        g_w2t_sd[o * NCAT + k] = sdw2[i];
    }
}

// ---------------------------------------------------------------------------
// Kernel A: H_pre[10240,2048] = X_slice @ [ld_w1 | sd_w1] + [ld_b1 | sd_b1]
// Classic fp32 SGEMM: BM=128 BN=128 BK=16, 8x8 microtile, 256 threads.
// ---------------------------------------------------------------------------
#define BM 128
#define BN 128
#define BK 16
#define TM 8
#define TN 8

__global__ __launch_bounds__(256, 2)
void k_gemm1(const float* __restrict__ hidden,
             const float* __restrict__ ldw1, const float* __restrict__ ldb1,
             const float* __restrict__ sdw1, const float* __restrict__ sdb1,
             const int* __restrict__ ctx)
{
    __shared__ float As[BK][BM + 4];
    __shared__ float Bs[BK][BN];

    const int tid = threadIdx.x;
    const int bx = blockIdx.x;   // 0..15 : column tile of H_pre
    const int by = blockIdx.y;   // 0..79 : row tile
    const int kp_start = ctx[0] - 1;

    const float* W    = (bx < 8) ? ldw1 : sdw1;
    const float* bias = (bx < 8) ? ldb1 : sdb1;
    const int nloc0   = (bx < 8) ? bx * BN : (bx - 8) * BN;

    const int m0 = by * BM;

    // A-tile loads: 2 float4 per thread, rows a_row and a_row+64
    const int a_row = tid >> 2;            // 0..63
    const int a_c4  = (tid & 3) * 4;       // 0,4,8,12
    size_t rowA0, rowA1;
    {
        int m = m0 + a_row;
        int b = m / T_, t = m - b * T_;
        rowA0 = (size_t)(b * S_ + kp_start + t) * E_;
        m += 64; b = m / T_; t = m - b * T_;
        rowA1 = (size_t)(b * S_ + kp_start + t) * E_;
    }
    // B-tile loads: 2 float4 per thread (k rows b_k and b_k+8)
    const int b_k  = tid >> 5;             // 0..7
    const int b_n4 = (tid & 31) * 4;       // 0..124

    const int tx = tid & 15;
    const int ty = tid >> 4;

    float acc[TM][TN];
#pragma unroll
    for (int i = 0; i < TM; i++)
#pragma unroll
        for (int j = 0; j < TN; j++) acc[i][j] = 0.f;

    for (int k0 = 0; k0 < E_; k0 += BK) {
        float4 a0 = *(const float4*)(hidden + rowA0 + k0 + a_c4);
        float4 a1 = *(const float4*)(hidden + rowA1 + k0 + a_c4);
        As[a_c4 + 0][a_row]      = a0.x;
        As[a_c4 + 1][a_row]      = a0.y;
        As[a_c4 + 2][a_row]      = a0.z;
        As[a_c4 + 3][a_row]      = a0.w;
        As[a_c4 + 0][a_row + 64] = a1.x;
        As[a_c4 + 1][a_row + 64] = a1.y;
        As[a_c4 + 2][a_row + 64] = a1.z;
        As[a_c4 + 3][a_row + 64] = a1.w;

        float4 w0 = *(const float4*)(W + (size_t)(k0 + b_k)     * H_ + nloc0 + b_n4);
        float4 w1 = *(const float4*)(W + (size_t)(k0 + b_k + 8) * H_ + nloc0 + b_n4);
        *(float4*)&Bs[b_k][b_n4]     = w0;
        *(float4*)&Bs[b_k + 8][b_n4] = w1;
        __syncthreads();

#pragma unroll
        for (int kk = 0; kk < BK; kk++) {
            float4 ra0 = *(const float4*)&As[kk][ty * TM];
            float4 ra1 = *(const float4*)&As[kk][ty * TM + 4];
            float4 rb0 = *(const float4*)&Bs[kk][tx * TN];
            float4 rb1 = *(const float4*)&Bs[kk][tx * TN + 4];
            float ra[8] = {ra0.x, ra0.y, ra0.z, ra0.w, ra1.x, ra1.y, ra1.z, ra1.w};
            float rb[8] = {rb0.x, rb0.y, rb0.z, rb0.w, rb1.x, rb1.y, rb1.z, rb1.w};
#pragma unroll
            for (int i = 0; i < TM; i++)
#pragma unroll
                for (int j = 0; j < TN; j++)
                    acc[i][j] = fmaf(ra[i], rb[j], acc[i][j]);
        }
        __syncthreads();
    }

    // epilogue: add bias, store
#pragma unroll
    for (int i = 0; i < TM; i++) {
        int m = m0 + ty * TM + i;
        float* dst = g_Hpre + (size_t)m * NTOT + bx * BN + tx * TN;
        float4 o0, o1;
        o0.x = acc[i][0] + bias[nloc0 + tx * TN + 0];
        o0.y = acc[i][1] + bias[nloc0 + tx * TN + 1];
        o0.z = acc[i][2] + bias[nloc0 + tx * TN + 2];
        o0.w = acc[i][3] + bias[nloc0 + tx * TN + 3];
        o1.x = acc[i][4] + bias[nloc0 + tx * TN + 4];
        o1.y = acc[i][5] + bias[nloc0 + tx * TN + 5];
        o1.z = acc[i][6] + bias[nloc0 + tx * TN + 6];
        o1.w = acc[i][7] + bias[nloc0 + tx * TN + 7];
        *(float4*)dst       = o0;
        *(float4*)(dst + 4) = o1;
    }
}

// ---------------------------------------------------------------------------
// Kernel B: per-row LayerNorm + relu + GEMM2 (out = cat([x,h]) @ w2 + b2)
// One block (256 thr) per row. Writes logits and scores directly into d_out.
// ---------------------------------------------------------------------------
__global__ __launch_bounds__(256)
void k_ln_gemm2(const float* __restrict__ hidden,
                const float* __restrict__ ldg, const float* __restrict__ ldbeta,
                const float* __restrict__ ldb2,
                const float* __restrict__ sdg, const float* __restrict__ sdbeta,
                const float* __restrict__ sdb2,
                const int* __restrict__ ctx,
                float* __restrict__ out)
{
    __shared__ float xs[E_];
    __shared__ float actld[H_];
    __shared__ float actsd[H_];
    __shared__ float red[8][4];
    __shared__ float stats[4];

    const int m   = blockIdx.x;
    const int tid = threadIdx.x;
    const int kp_start = ctx[0] - 1;
    const int b = m / T_, t = m - b * T_;
    const float* xrow = hidden + (size_t)(b * S_ + kp_start + t) * E_;
    xs[tid] = xrow[tid];                       // 256 threads == E_

    const float* hrow = g_Hpre + (size_t)m * NTOT;
    float hl[4], hs[4];
    float s1 = 0.f, s2 = 0.f, s3 = 0.f, s4 = 0.f;
#pragma unroll
    for (int i = 0; i < 4; i++) {
        int j = tid + 256 * i;
        hl[i] = hrow[j];
        hs[i] = hrow[H_ + j];
        s1 += hl[i]; s2 += hl[i] * hl[i];
        s3 += hs[i]; s4 += hs[i] * hs[i];
    }
#pragma unroll
    for (int o = 16; o; o >>= 1) {
        s1 += __shfl_down_sync(0xffffffffu, s1, o);
        s2 += __shfl_down_sync(0xffffffffu, s2, o);
        s3 += __shfl_down_sync(0xffffffffu, s3, o);
        s4 += __shfl_down_sync(0xffffffffu, s4, o);
    }
    const int w = tid >> 5, l = tid & 31;
    if (l == 0) { red[w][0] = s1; red[w][1] = s2; red[w][2] = s3; red[w][3] = s4; }
    __syncthreads();
    if (tid == 0) {
        float a = 0.f, bb = 0.f, c = 0.f, d = 0.f;
        for (int i = 0; i < 8; i++) { a += red[i][0]; bb += red[i][1]; c += red[i][2]; d += red[i][3]; }
        float mul = a / H_, mus = c / H_;
        float varl = bb / H_ - mul * mul;
        float vars = d / H_ - mus * mus;
        stats[0] = mul; stats[1] = rsqrtf(varl + 1e-5f);
        stats[2] = mus; stats[3] = rsqrtf(vars + 1e-5f);
    }
    __syncthreads();
    const float mul = stats[0], rl = stats[1], mus = stats[2], rs = stats[3];
#pragma unroll
    for (int i = 0; i < 4; i++) {
        int j = tid + 256 * i;
        float a = ldg[j] * (hl[i] - mul) * rl + ldbeta[j];
        actld[j] = fmaxf(a, 0.f);
        float c = sdg[j] * (hs[i] - mus) * rs + sdbeta[j];
        actsd[j] = fmaxf(c, 0.f);
    }
    __syncthreads();

    // GEMM2: warps 0-5 -> 12 logits outputs, warps 6-7 -> 6 score outputs.
    if (w < 6) {
#pragma unroll
        for (int oo = 0; oo < 2; oo++) {
            const int o = 2 * w + oo;
            const float* wcol = g_w2t_ld + (size_t)o * NCAT;
            float acc = 0.f;
#pragma unroll
            for (int i = 0; i < 40; i++) {
                int k = l + 32 * i;
                float v = (k < E_) ? xs[k] : actld[k - E_];
                acc = fmaf(v, __ldg(wcol + k), acc);
            }
#pragma unroll
            for (int off = 16; off; off >>= 1) acc += __shfl_down_sync(0xffffffffu, acc, off);
            if (l == 0) out[OFF_LOGITS + (size_t)m * 12 + o] = acc + __ldg(ldb2 + o);
        }
    } else {
#pragma unroll
        for (int oo = 0; oo < 3; oo++) {
            const int o = 3 * (w - 6) + oo;
            const float* wcol = g_w2t_sd + (size_t)o * NCAT;
            float acc = 0.f;
#pragma unroll
            for (int i = 0; i < 40; i++) {
                int k = l + 32 * i;
                float v = (k < E_) ? xs[k] : actsd[k - E_];
                acc = fmaf(v, __ldg(wcol + k), acc);
            }
#pragma unroll
            for (int off = 16; off; off >>= 1) acc += __shfl_down_sync(0xffffffffu, acc, off);
            if (l == 0) out[OFF_SCORES + (size_t)m * 6 + o] = acc + __ldg(sdb2 + o);
        }
    }
}

// ---------------------------------------------------------------------------
// Kernel C: per-(b,t) loss: min/argmin over K modes, double-softmax CE, selected
// ---------------------------------------------------------------------------
__global__ void k_loss(const float* __restrict__ fkp, float* __restrict__ out)
{
    int m = blockIdx.x * blockDim.x + threadIdx.x;
    if (m >= M_TOT) return;

    const float* lg = out + OFF_LOGITS + (size_t)m * 12;
    const float* sc = out + OFF_SCORES + (size_t)m * 6;
    float fx = fkp[m * 2 + 0], fy = fkp[m * 2 + 1];

    float l[12], s[6];
#pragma unroll
    for (int i = 0; i < 12; i++) l[i] = lg[i];
#pragma unroll
    for (int i = 0; i < 6; i++)  s[i] = sc[i];

    float best = 3.4e38f; int bi = 0;
#pragma unroll
    for (int k = 0; k < K_; k++) {
        float dx = l[2 * k] - fx, dy = l[2 * k + 1] - fy;
        float v = dx * dx + dy * dy;
        if (v < best) { best = v; bi = k; }
    }

    // softmax(scores)
    float mx = s[0];
#pragma unroll
    for (int k = 1; k < K_; k++) mx = fmaxf(mx, s[k]);
    float Z = 0.f, e[6];
#pragma unroll
    for (int k = 0; k < K_; k++) { e[k] = expf(s[k] - mx); Z += e[k]; }
    float sm[6];
#pragma unroll
    for (int k = 0; k < K_; k++) sm[k] = e[k] / Z;
    // log_softmax(softmax(scores)) at index bi
    float mx2 = sm[0];
#pragma unroll
    for (int k = 1; k < K_; k++) mx2 = fmaxf(mx2, sm[k]);
    float Z2 = 0.f;
#pragma unroll
    for (int k = 0; k < K_; k++) Z2 += expf(sm[k] - mx2);
    float ce = -(sm[bi] - mx2 - logf(Z2));

    out[OFF_SEL + (size_t)m * 2 + 0] = l[2 * bi];
    out[OFF_SEL + (size_t)m * 2 + 1] = l[2 * bi + 1];
    g_minloss[m] = best;
    g_ce[m]      = ce;
}

// ---------------------------------------------------------------------------
// Kernel D: deterministic reduction over B per t, loss_per_kp and kp_loss
// ---------------------------------------------------------------------------
__global__ void k_loss_reduce(float* __restrict__ out)
{
    __shared__ float red[16];
    __shared__ float lpk[T_];
    const int tid = threadIdx.x;
    const float wt[T_] = {1e-4f, 1e-3f, 1e-2f, 1e-1f, 1.f};

    for (int t = 0; t < T_; t++) {
        float sm = 0.f, sc = 0.f;
        for (int b = tid; b < B_; b += 256) {
            sm += g_minloss[b * T_ + t];
            sc += g_ce[b * T_ + t];
        }
#pragma unroll
        for (int o = 16; o; o >>= 1) {
            sm += __shfl_down_sync(0xffffffffu, sm, o);
            sc += __shfl_down_sync(0xffffffffu, sc, o);
        }
        int w = tid >> 5, l = tid & 31;
        if (l == 0) { red[w] = sm; red[w + 8] = sc; }
        __syncthreads();
        if (tid == 0) {
            float a = 0.f, c = 0.f;
            for (int i = 0; i < 8; i++) { a += red[i]; c += red[i + 8]; }
            float v = (a / (float)B_) * wt[t] + c / (float)B_;
            lpk[t] = v;
            out[OFF_LPK + t] = v;
        }
        __syncthreads();
    }
    if (tid == 0) {
        float s = 0.f;
        for (int t = 0; t < T_; t++) s += lpk[t];
        out[0] = s / (float)T_;
    }
}

// ---------------------------------------------------------------------------
extern "C" void kernel_launch(void* const* d_in, const int* in_sizes, int n_in,
                              void* d_out, int out_size)
{
    const float* hidden  = (const float*)d_in[0];
    const float* fkp     = (const float*)d_in[1];
    const float* ld_w1   = (const float*)d_in[2];
    const float* ld_b1   = (const float*)d_in[3];
    const float* ld_g    = (const float*)d_in[4];
    const float* ld_be   = (const float*)d_in[5];
    const float* ld_w2   = (const float*)d_in[6];
    const float* ld_b2   = (const float*)d_in[7];
    const float* sd_w1   = (const float*)d_in[8];
    const float* sd_b1   = (const float*)d_in[9];
    const float* sd_g    = (const float*)d_in[10];
    const float* sd_be   = (const float*)d_in[11];
    const float* sd_w2   = (const float*)d_in[12];
    const float* sd_b2   = (const float*)d_in[13];
    const int*   ctx     = (const int*)d_in[14];
    float* out = (float*)d_out;

    k_w2t<<<(12 * NCAT + 255) / 256, 256>>>(ld_w2, sd_w2);
    dim3 gridA(NTOT / BN, M_TOT / BM);   // (16, 80)
    k_gemm1<<<gridA, 256>>>(hidden, ld_w1, ld_b1, sd_w1, sd_b1, ctx);
    k_ln_gemm2<<<M_TOT, 256>>>(hidden, ld_g, ld_be, ld_b2, sd_g, sd_be, sd_b2, ctx, out);
    k_loss<<<(M_TOT + 255) / 256, 256>>>(fkp, out);
    k_loss_reduce<<<1, 256>>>(out);
}